// round 11
// baseline (speedup 1.0000x reference)
#include <cuda_runtime.h>
#include <cstdint>

// Windowed 3x3x3 correlation:
//   out[o=(i*9+j*3+k)][z][y][x] = (1/sqrt(32)) * sum_c fixed[c,z,y,x] * moving[c, z+i-1, y+j-1, x+k-1]
// fixed, moving: [32][96][96][96] fp32 (zero padding outside volume)
//
// Offset-group split: threadIdx.z = gi in {0,1,2} handles the 9 offsets with
// z-offset i == gi. Voxel tile per CTA: 32 (x, VEC=2) x 8 (y) x 1 (z).
// 384 threads, 18 acc regs/thread -> 3 CTAs/SM (36 warps).

#define N 96
#define C 32
#define VOL (96 * 96 * 96)

#define BTX 16
#define BTY 8
#define NGRP 3
#define NTHR 384
#define TILE_X 32        // BTX * 2
#define SMX_U 34         // used smem width (TILE_X + 2)
#define SMX 36           // padded stride: EVEN -> (row*SMX + tx*2) is 8B-aligned
#define SMY 10           // BTY + 2
#define SMZ 3            // z-window extent for a 1-deep voxel slab
#define BUFSZ (SMZ * SMY * SMX)       // 1080 floats per stage
#define SM_FILL (SMZ * SMY * SMX_U)   // 1020 elements to fill
#define NSLOT 3          // ceil(1020 / 384)
#define TAIL_TID 252     // slot 2 active iff tid < 1020 - 768
#define STAGES 4

__device__ __forceinline__ void cp_async4(uint32_t saddr, const float* gsrc, int srcsize) {
    asm volatile("cp.async.ca.shared.global [%0], [%1], 4, %2;\n"
                 :: "r"(saddr), "l"(gsrc), "r"(srcsize));
}
__device__ __forceinline__ void cp_commit() {
    asm volatile("cp.async.commit_group;\n" ::: "memory");
}
__device__ __forceinline__ void cp_wait2() {
    asm volatile("cp.async.wait_group 2;\n" ::: "memory");
}

// Packed f32x2 FMA (B300 FFMA2 — only reachable via PTX fma.rn.f32x2)
__device__ __forceinline__ void ffma2(unsigned long long& d,
                                      unsigned long long a,
                                      unsigned long long b) {
    asm("fma.rn.f32x2 %0, %1, %2, %0;" : "+l"(d) : "l"(a), "l"(b));
}
__device__ __forceinline__ unsigned long long pack2(float lo, float hi) {
    unsigned long long r;
    asm("mov.b64 %0, {%1, %2};"
        : "=l"(r) : "r"(__float_as_uint(lo)), "r"(__float_as_uint(hi)));
    return r;
}

__global__ __launch_bounds__(NTHR, 3)
void wincorr_kernel(const float* __restrict__ fixedp,
                    const float* __restrict__ movingp,
                    float* __restrict__ out)
{
    __shared__ float sm[STAGES * BUFSZ];

    const int tx = threadIdx.x;                  // 0..15
    const int ty = threadIdx.y;                  // 0..7
    const int gi = threadIdx.z;                  // 0..2  (window z-offset group)
    const int tid = tx + BTX * (ty + BTY * gi);  // 0..383

    const int x0 = blockIdx.x * TILE_X;
    const int y0 = blockIdx.y * BTY;
    const int z0 = blockIdx.z;                   // 1-deep z slab

    const int x = x0 + tx * 2;
    const int y = y0 + ty;

    // ---- Hoisted halo-fill metadata (channel-invariant). Slots 0,1 always
    // active; slot 2 active iff tid < TAIL_TID. ----
    uint32_t smaddr[NSLOT];
    int      gmoff[NSLOT];
    int      szsrc[NSLOT];      // 4 if in-bounds else 0 (zero-fill)
#pragma unroll
    for (int s = 0; s < NSLOT; s++) {
        int idx = tid + s * NTHR;
        if (idx >= SM_FILL) idx = 0;             // dummy (predicated off at use)
        int lz = idx / (SMY * SMX_U);
        int r  = idx - lz * (SMY * SMX_U);
        int ly = r / SMX_U;
        int lx = r - ly * SMX_U;
        int gz = z0 - 1 + lz;
        int gy = y0 - 1 + ly;
        int gx = x0 - 1 + lx;
        bool in = (unsigned)gz < (unsigned)N && (unsigned)gy < (unsigned)N &&
                  (unsigned)gx < (unsigned)N;
        int smoff = (lz * SMY + ly) * SMX + lx;
        smaddr[s] = (uint32_t)__cvta_generic_to_shared(sm + smoff);
        gmoff[s]  = in ? (gz * N + gy) * N + gx : 0;
        szsrc[s]  = in ? 4 : 0;
    }
    const bool tail = (tid < TAIL_TID);

    // 9 offsets for this group: (j,k). k=0 and k=2 use packed accs, k=1 scalar.
    unsigned long long acc0[3], acc2[3];   // k=0 / k=2, per j
    float acc1a[3], acc1b[3];              // k=1 halves, per j
#pragma unroll
    for (int j = 0; j < 3; j++) {
        acc0[j] = 0ULL; acc2[j] = 0ULL;
        acc1a[j] = 0.f; acc1b[j] = 0.f;
    }

    const float* fptr = fixedp + ((z0 * N) + y) * N + x;

    // ---- Prologue: prefetch channels 0..2 into stages 0..2, fixed 0..1 ----
#pragma unroll
    for (int p = 0; p < STAGES - 1; p++) {
        const float* mv = movingp + p * VOL;
        const uint32_t bofs = p * (BUFSZ * 4u);
#pragma unroll
        for (int s = 0; s < NSLOT; s++)
            if (s < 2 || tail) cp_async4(smaddr[s] + bofs, mv + gmoff[s], szsrc[s]);
        cp_commit();
    }
    float2 fv0 = *reinterpret_cast<const float2*>(fptr);
    float2 fv1 = *reinterpret_cast<const float2*>(fptr + VOL);

    for (int c = 0; c < C; c++) {
        cp_wait2();              // stage for channel c landed (<=2 newer groups pending)
        __syncthreads();         // all warps done reading stage (c-1)&3

        // Prefetch channel c+3 into stage (c+3)&3.
        if (c + 3 < C) {
            const uint32_t bofs = ((c + 3) & (STAGES - 1)) * (BUFSZ * 4u);
            const float* nxt = movingp + (c + 3) * VOL;
#pragma unroll
            for (int s = 0; s < NSLOT; s++)
                if (s < 2 || tail) cp_async4(smaddr[s] + bofs, nxt + gmoff[s], szsrc[s]);
        }
        cp_commit();             // uniform commit (empty groups keep wait count valid)

        const float2 f = fv0;
        fv0 = fv1;
        if (c + 2 < C)
            fv1 = *reinterpret_cast<const float2*>(fptr + (c + 2) * VOL);

        const unsigned long long fp = pack2(f.x, f.y);
        const float* buf = sm + (c & (STAGES - 1)) * BUFSZ;
        // This group's z-row: lz = gi (gz = z0 - 1 + gi = z + gi - 1).
        const float* rowbase = buf + (gi * SMY) * SMX + tx * 2;

#pragma unroll
        for (int j = 0; j < 3; j++) {
            // window cols tx*2 .. tx*2+3  <->  gx = x-1 .. x+2  (8B-aligned, conflict-free)
            const float* row = rowbase + (ty + j) * SMX;
            const unsigned long long w01 =
                *reinterpret_cast<const unsigned long long*>(row);       // (m[x-1], m[x])
            const unsigned long long w23 =
                *reinterpret_cast<const unsigned long long*>(row + 2);   // (m[x+1], m[x+2])
            ffma2(acc0[j], fp, w01);    // k=0
            ffma2(acc2[j], fp, w23);    // k=2
            // k=1 uses the cross pair (m[x], m[x+1]) = (hi(w01), lo(w23)) — scalar FFMA, no packs.
            float w1, w2;
            asm("{ .reg .b32 t; mov.b64 {t, %0}, %1; }" : "=r"(*(unsigned*)&w1) : "l"(w01));
            asm("{ .reg .b32 t; mov.b64 {%0, t}, %1; }" : "=r"(*(unsigned*)&w2) : "l"(w23));
            acc1a[j] = fmaf(f.x, w1, acc1a[j]);
            acc1b[j] = fmaf(f.y, w2, acc1b[j]);
        }
    }

    const float scale = 0.17677669529663687f;  // 32^{-1/2}
    const int sp = (z0 * N + y) * N + x;
    float* outg = out + (gi * 9) * VOL + sp;
#pragma unroll
    for (int j = 0; j < 3; j++) {
        unsigned int lo, hi;
        float2 r;

        asm("mov.b64 {%0, %1}, %2;" : "=r"(lo), "=r"(hi) : "l"(acc0[j]));
        r.x = __uint_as_float(lo) * scale;
        r.y = __uint_as_float(hi) * scale;
        *reinterpret_cast<float2*>(outg + (j * 3 + 0) * VOL) = r;

        r.x = acc1a[j] * scale;
        r.y = acc1b[j] * scale;
        *reinterpret_cast<float2*>(outg + (j * 3 + 1) * VOL) = r;

        asm("mov.b64 {%0, %1}, %2;" : "=r"(lo), "=r"(hi) : "l"(acc2[j]));
        r.x = __uint_as_float(lo) * scale;
        r.y = __uint_as_float(hi) * scale;
        *reinterpret_cast<float2*>(outg + (j * 3 + 2) * VOL) = r;
    }
}

extern "C" void kernel_launch(void* const* d_in, const int* in_sizes, int n_in,
                              void* d_out, int out_size)
{
    const float* fixedp  = (const float*)d_in[0];
    const float* movingp = (const float*)d_in[1];
    float* out = (float*)d_out;

    dim3 block(BTX, BTY, NGRP);          // 384 threads
    dim3 grid(N / TILE_X, N / BTY, N);   // 3 x 12 x 96 = 3456 blocks
    wincorr_kernel<<<grid, block>>>(fixedp, movingp, out);
}

// round 12
// speedup vs baseline: 1.0883x; 1.0883x over previous
#include <cuda_runtime.h>
#include <cstdint>

// Windowed 3x3x3 correlation, z-marching ring kernel.
//   out[o=(i*9+j*3+k)][z][y][x] = (1/sqrt(32)) * sum_c fixed[c,z,y,x] * moving[c, z+i-1, y+j-1, x+k-1]
// fixed, moving: [32][96][96][96] fp32, zero padding outside.
//
// CTA: xy tile 32x8 (VEC=2 in x), marches 24 z-steps. Smem ring: 4 z-plane-slots,
// each slot = 32 channels x (10y x 34x) halo plane. Channel work split 16/16 across
// threadIdx.z; partial sums combined in smem once per z-step. Grid 3x12x4 = 144 CTAs
// (single wave on 148 SMs).

#define N 96
#define NN (N * N)
#define C 32
#define VOL (N * N * N)

#define BTX 16
#define BTY 8
#define NCZ 2
#define NTHR 256
#define TILE_X 32
#define PLX 34                       // halo plane x extent (stride; even -> 8B-aligned rows)
#define PLY 10                       // halo plane y extent
#define PLANE (PLX * PLY)            // 340 floats per (channel, z-plane)
#define SLOT_FLOATS (PLANE * C)      // 10880 floats per ring slot
#define SLOT_BYTES (SLOT_FLOATS * 4) // 43520
#define CH_BYTES (PLANE * 4)         // 1360
#define RING 4
#define ZSPLIT 4
#define ZSTEPS (N / ZSPLIT)          // 24
#define CHALF 16
#define RED_OFF (RING * SLOT_FLOATS)            // 43520 floats
#define SMEM_FLOATS (RED_OFF + 27 * 128 * 2)    // + reduction buffer = 50432
#define SMEM_BYTES (SMEM_FLOATS * 4)            // 201728 B

typedef unsigned long long u64;

__device__ __forceinline__ void cp_async4(uint32_t saddr, const float* gsrc, int srcsize) {
    asm volatile("cp.async.ca.shared.global [%0], [%1], 4, %2;\n"
                 :: "r"(saddr), "l"(gsrc), "r"(srcsize));
}
__device__ __forceinline__ void cp_commit() {
    asm volatile("cp.async.commit_group;\n" ::: "memory");
}
__device__ __forceinline__ void cp_wait1() {
    asm volatile("cp.async.wait_group 1;\n" ::: "memory");
}

__device__ __forceinline__ u64 pack2(float lo, float hi) {
    u64 r;
    asm("mov.b64 %0, {%1, %2};" : "=l"(r) : "f"(lo), "f"(hi));
    return r;
}
__device__ __forceinline__ u64 f2u(float2 v) {
    u64 r;
    asm("mov.b64 %0, {%1, %2};" : "=l"(r) : "f"(v.x), "f"(v.y));
    return r;
}
__device__ __forceinline__ void ffma2(u64& d, u64 a, u64 b) {
    asm("fma.rn.f32x2 %0, %1, %2, %0;" : "+l"(d) : "l"(a), "l"(b));
}
__device__ __forceinline__ u64 addf2(u64 a, u64 b) {
    u64 r; asm("add.rn.f32x2 %0, %1, %2;" : "=l"(r) : "l"(a), "l"(b)); return r;
}
__device__ __forceinline__ u64 mulf2(u64 a, u64 b) {
    u64 r; asm("mul.rn.f32x2 %0, %1, %2;" : "=l"(r) : "l"(a), "l"(b)); return r;
}

__global__ __launch_bounds__(NTHR, 1)
void wincorr_kernel(const float* __restrict__ fixedp,
                    const float* __restrict__ movingp,
                    float* __restrict__ out)
{
    extern __shared__ float sm[];
    float* red = sm + RED_OFF;

    const int tx = threadIdx.x;                  // 0..15
    const int ty = threadIdx.y;                  // 0..7
    const int cz = threadIdx.z;                  // 0..1 (channel half)
    const int tid = tx + BTX * (ty + BTY * cz);  // 0..255
    const int v = ty * BTX + tx;                 // voxel-pair id 0..127

    const int x0 = blockIdx.x * TILE_X;
    const int y0 = blockIdx.y * BTY;
    const int zbase = blockIdx.z * ZSTEPS;

    const int x = x0 + tx * 2;
    const int y = y0 + ty;

    // ---- Fill metadata: each thread owns 1-2 halo (ly,lx) positions, loops channels ----
    const uint32_t smbase = (uint32_t)__cvta_generic_to_shared(sm);
    const int pos0 = tid;                        // < 340 always
    const int ly0 = pos0 / PLX, lx0 = pos0 - ly0 * PLX;
    const int gy0 = y0 - 1 + ly0, gx0 = x0 - 1 + lx0;
    const bool vin0 = (unsigned)gy0 < N && (unsigned)gx0 < N;
    const int go0 = vin0 ? gy0 * N + gx0 : 0;
    const uint32_t d0 = smbase + pos0 * 4;

    const bool has1 = tid < (PLANE - NTHR);      // tid < 84
    const int pos1 = has1 ? tid + NTHR : 0;
    const int ly1 = pos1 / PLX, lx1 = pos1 - ly1 * PLX;
    const int gy1 = y0 - 1 + ly1, gx1 = x0 - 1 + lx1;
    const bool vin1 = (unsigned)gy1 < N && (unsigned)gx1 < N;
    const int go1 = vin1 ? gy1 * N + gx1 : 0;
    const uint32_t d1 = smbase + pos1 * 4;

    auto fill_plane = [&](int q) {
        const bool zin = (unsigned)q < N;
        const int qq = zin ? q : 0;
        const uint32_t sofs = (uint32_t)(q & 3) * SLOT_BYTES;
        {
            const int sz = (vin0 && zin) ? 4 : 0;
            const float* s = movingp + qq * NN + go0;
            uint32_t d = d0 + sofs;
#pragma unroll 8
            for (int c2 = 0; c2 < C; c2++) { cp_async4(d, s, sz); d += CH_BYTES; s += VOL; }
        }
        if (has1) {
            const int sz = (vin1 && zin) ? 4 : 0;
            const float* s = movingp + qq * NN + go1;
            uint32_t d = d1 + sofs;
#pragma unroll 8
            for (int c2 = 0; c2 < C; c2++) { cp_async4(d, s, sz); d += CH_BYTES; s += VOL; }
        }
    };

    const float* fcol = fixedp + (cz * CHALF) * VOL + y * N + x;
    float* ocol = out + y * N + x;
    const int rowoff = ty * PLX + tx * 2;
    const float* sbase = sm + (cz * CHALF) * PLANE + rowoff;
    const float scale = 0.17677669529663687f;    // 32^{-1/2}
    const u64 scl2 = pack2(scale, scale);

    // ---- Prologue: planes zbase-1 .. zbase+1 ----
    for (int p = zbase - 1; p <= zbase + 1; ++p) {
        fill_plane(p);
        cp_commit();
    }

    for (int zi = 0; zi < ZSTEPS; ++zi) {
        const int z = zbase + zi;
        __syncthreads();                 // step z-1 readers done with slot (z+2)&3 / red buffer

        const int q = z + 2;
        if (q <= zbase + ZSTEPS) fill_plane(q);
        cp_commit();                     // uniform commit (possibly empty)
        cp_wait1();                      // plane z+1 complete (only newest group pending)
        __syncthreads();                 // all threads' fills visible

        // fixed values for this half's 16 channels (batched LDG, latency amortized per step)
        float2 f[CHALF];
        const float* fp = fcol + z * NN;
#pragma unroll
        for (int h = 0; h < CHALF; h++) f[h] = *reinterpret_cast<const float2*>(fp + h * VOL);

        u64 accA[9], accC[9];
        float a1x[9], a1y[9];
#pragma unroll
        for (int oi = 0; oi < 9; oi++) { accA[oi] = 0ULL; accC[oi] = 0ULL; a1x[oi] = 0.f; a1y[oi] = 0.f; }

        const float* b0 = sbase + ((z - 1) & 3) * SLOT_FLOATS;
        const float* b1 = sbase + ((z    ) & 3) * SLOT_FLOATS;
        const float* b2 = sbase + ((z + 1) & 3) * SLOT_FLOATS;

#pragma unroll 4
        for (int h = 0; h < CHALF; ++h) {
            const float2 fv = f[h];
            const u64 fpk = f2u(fv);
            const float* p0 = b0 + h * PLANE;
            const float* p1 = b1 + h * PLANE;
            const float* p2 = b2 + h * PLANE;

#define ROWSET(P, OB)                                                          \
            {                                                                  \
                _Pragma("unroll")                                              \
                for (int j = 0; j < 3; j++) {                                  \
                    const float* r = (P) + j * PLX;                            \
                    const float2 m01 = *reinterpret_cast<const float2*>(r);    \
                    const float2 m23 = *reinterpret_cast<const float2*>(r + 2);\
                    const int oi = (OB) + j;                                   \
                    ffma2(accA[oi], fpk, f2u(m01));                            \
                    ffma2(accC[oi], fpk, f2u(m23));                            \
                    a1x[oi] = fmaf(fv.x, m01.y, a1x[oi]);                      \
                    a1y[oi] = fmaf(fv.y, m23.x, a1y[oi]);                      \
                }                                                              \
            }
            ROWSET(p0, 0)
            ROWSET(p1, 3)
            ROWSET(p2, 6)
#undef ROWSET
        }

        // ---- Combine halves: cz=1 stores partials, cz=0 adds + writes out ----
        if (cz == 1) {
#pragma unroll
            for (int oi = 0; oi < 9; oi++) {
                *reinterpret_cast<u64*>(&red[(oi * 3 + 0) * 256 + 2 * v]) = accA[oi];
                *reinterpret_cast<float2*>(&red[(oi * 3 + 1) * 256 + 2 * v]) =
                    make_float2(a1x[oi], a1y[oi]);
                *reinterpret_cast<u64*>(&red[(oi * 3 + 2) * 256 + 2 * v]) = accC[oi];
            }
        }
        __syncthreads();
        if (cz == 0) {
            float* op = ocol + z * NN;
#pragma unroll
            for (int oi = 0; oi < 9; oi++) {
                const u64 rA = *reinterpret_cast<const u64*>(&red[(oi * 3 + 0) * 256 + 2 * v]);
                *reinterpret_cast<u64*>(op + (oi * 3 + 0) * VOL) = mulf2(addf2(accA[oi], rA), scl2);

                const float2 r1 = *reinterpret_cast<const float2*>(&red[(oi * 3 + 1) * 256 + 2 * v]);
                float2 o1;
                o1.x = (a1x[oi] + r1.x) * scale;
                o1.y = (a1y[oi] + r1.y) * scale;
                *reinterpret_cast<float2*>(op + (oi * 3 + 1) * VOL) = o1;

                const u64 rC = *reinterpret_cast<const u64*>(&red[(oi * 3 + 2) * 256 + 2 * v]);
                *reinterpret_cast<u64*>(op + (oi * 3 + 2) * VOL) = mulf2(addf2(accC[oi], rC), scl2);
            }
        }
    }
}

extern "C" void kernel_launch(void* const* d_in, const int* in_sizes, int n_in,
                              void* d_out, int out_size)
{
    const float* fixedp  = (const float*)d_in[0];
    const float* movingp = (const float*)d_in[1];
    float* out = (float*)d_out;

    cudaFuncSetAttribute(wincorr_kernel,
                         cudaFuncAttributeMaxDynamicSharedMemorySize, SMEM_BYTES);

    dim3 block(BTX, BTY, NCZ);                    // 256 threads
    dim3 grid(N / TILE_X, N / BTY, ZSPLIT);       // 3 x 12 x 4 = 144 blocks (1 wave)
    wincorr_kernel<<<grid, block, SMEM_BYTES>>>(fixedp, movingp, out);
}

// round 15
// speedup vs baseline: 1.4319x; 1.3157x over previous
#include <cuda_runtime.h>
#include <cstdint>

// Windowed 3x3x3 correlation:
//   out[o=(i*9+j*3+k)][z][y][x] = (1/sqrt(32)) * sum_c fixed[c,z,y,x] * moving[c, z+i-1, y+j-1, x+k-1]
// fixed, moving: [32][96][96][96] fp32 (zero padding outside volume)
//
// R10 structure (best: 137.7us) + 2 channels per pipeline stage (16 sync points
// instead of 32) + low-ALU inner loop (FFMA2 pairs + scalar cross).
// R14 bug fixed: ring stage indices now computed with proper mod-3 counters.

#define N 96
#define C 32
#define VOL (96 * 96 * 96)

#define BTX 16
#define BTY 8
#define BTZ 2
#define NTHR 256
#define TILE_X 32        // BTX * 2
#define SMX_U 34         // used smem width (TILE_X + 2)
#define SMX 36           // padded stride: EVEN -> (row*SMX + tx*2) is 8B-aligned
#define SMY 10           // BTY + 2
#define SMZ 4            // BTZ + 2
#define BUFSZ (SMZ * SMY * SMX)       // 1440 floats per channel tile
#define SM_FILL (SMZ * SMY * SMX_U)   // 1360 elements per channel tile
#define NSLOT 6          // ceil(1360 / 256)
#define STAGES 3         // ring stages; each stage holds CPS channel tiles
#define CPS 2            // channels per stage
#define NITER (C / CPS)  // 16 pipeline iterations

typedef unsigned long long u64;

__device__ __forceinline__ void cp_async4(uint32_t saddr, const float* gsrc, int srcsize) {
    asm volatile("cp.async.ca.shared.global [%0], [%1], 4, %2;\n"
                 :: "r"(saddr), "l"(gsrc), "r"(srcsize));
}
__device__ __forceinline__ void cp_commit() {
    asm volatile("cp.async.commit_group;\n" ::: "memory");
}
__device__ __forceinline__ void cp_wait1() {
    asm volatile("cp.async.wait_group 1;\n" ::: "memory");
}

__device__ __forceinline__ u64 pack2(float lo, float hi) {
    u64 r;
    asm("mov.b64 %0, {%1, %2};" : "=l"(r) : "f"(lo), "f"(hi));
    return r;
}
__device__ __forceinline__ void ffma2(u64& d, u64 a, u64 b) {
    asm("fma.rn.f32x2 %0, %1, %2, %0;" : "+l"(d) : "l"(a), "l"(b));
}

__global__ __launch_bounds__(NTHR, 2)
void wincorr_kernel(const float* __restrict__ fixedp,
                    const float* __restrict__ movingp,
                    float* __restrict__ out)
{
    __shared__ float sm[STAGES * CPS * BUFSZ];

    const int tx = threadIdx.x;                  // 0..15
    const int ty = threadIdx.y;                  // 0..7
    const int tz = threadIdx.z;                  // 0..1
    const int tid = tx + BTX * (ty + BTY * tz);  // 0..255

    const int x0 = blockIdx.x * TILE_X;
    const int y0 = blockIdx.y * BTY;
    const int z0 = blockIdx.z * BTZ;

    const int x = x0 + tx * 2;
    const int y = y0 + ty;
    const int z = z0 + tz;

    // ---- Hoisted halo-fill metadata (channel-invariant) ----
    uint32_t smaddr[NSLOT];       // shared address of slot (stage 0, ch 0)
    int      gmoff[NSLOT];        // offset within one channel
    int      szsrc[NSLOT];        // 4 if in-bounds else 0 (zero-fill)
    bool     active[NSLOT];
#pragma unroll
    for (int s = 0; s < NSLOT; s++) {
        int idx = tid + s * NTHR;
        bool a = idx < SM_FILL;
        int cidx = a ? idx : 0;
        int lz = cidx / (SMY * SMX_U);
        int r  = cidx - lz * (SMY * SMX_U);
        int ly = r / SMX_U;
        int lx = r - ly * SMX_U;
        int gz = z0 - 1 + lz;
        int gy = y0 - 1 + ly;
        int gx = x0 - 1 + lx;
        bool in = (unsigned)gz < (unsigned)N && (unsigned)gy < (unsigned)N &&
                  (unsigned)gx < (unsigned)N;
        int smoff = (lz * SMY + ly) * SMX + lx;
        smaddr[s] = (uint32_t)__cvta_generic_to_shared(sm + smoff);
        gmoff[s]  = in ? (gz * N + gy) * N + gx : 0;
        szsrc[s]  = in ? 4 : 0;
        active[s] = a;
    }

    // Fill both channel tiles of one stage (channels c0, c0+1).
    auto fill_stage = [&](int stage, int c0) {
        const uint32_t bofs = (uint32_t)stage * (CPS * BUFSZ * 4u);
        const float* mv = movingp + c0 * VOL;
#pragma unroll
        for (int s = 0; s < NSLOT; s++) {
            if (active[s]) {
                cp_async4(smaddr[s] + bofs, mv + gmoff[s], szsrc[s]);
                cp_async4(smaddr[s] + bofs + BUFSZ * 4u, mv + VOL + gmoff[s], szsrc[s]);
            }
        }
    };

    // Accumulators: k=0 and k=2 packed (u64), k=1 scalar halves.  o = i*9+j*3+k.
    u64 accA[9], accC[9];
    float a1x[9], a1y[9];
#pragma unroll
    for (int oi = 0; oi < 9; oi++) { accA[oi] = 0ULL; accC[oi] = 0ULL; a1x[oi] = 0.f; a1y[oi] = 0.f; }

    const int fbase = ((z * N) + y) * N + x;
    const float* fptr = fixedp + fbase;

    // ---- Prologue: stages 0,1 <- channel pairs (0,1), (2,3); fixed pair 0 ----
    fill_stage(0, 0); cp_commit();
    fill_stage(1, 2); cp_commit();
    float2 fv0a = *reinterpret_cast<const float2*>(fptr);
    float2 fv0b = *reinterpret_cast<const float2*>(fptr + VOL);

    int cur = 0;                 // ring stage holding the current channel pair
    for (int t = 0; t < NITER; t++) {
        const int c = t * CPS;
        cp_wait1();              // stage 'cur' (channels c,c+1) landed
        __syncthreads();         // fills visible; prev readers done with fill target stage

        // Prefetch channel pair t+2 into stage (cur+2) mod 3.
        if (t + 2 < NITER) {
            int st = cur + 2; if (st >= STAGES) st -= STAGES;   // cur in [0,2] -> exact mod
            fill_stage(st, c + 4);
        }
        cp_commit();             // uniform commit (empty groups keep wait count valid)

        const float2 fa = fv0a;
        const float2 fb = fv0b;
        if (t + 1 < NITER) {
            fv0a = *reinterpret_cast<const float2*>(fptr + (c + 2) * VOL);
            fv0b = *reinterpret_cast<const float2*>(fptr + (c + 3) * VOL);
        }

        const float* stg = sm + cur * (CPS * BUFSZ);
        const int rowoff = tx * 2;

#pragma unroll
        for (int ch = 0; ch < CPS; ch++) {
            const float2 f = (ch == 0) ? fa : fb;
            const u64 fpk = pack2(f.x, f.y);
            const float* buf = stg + ch * BUFSZ;
#pragma unroll
            for (int i = 0; i < 3; i++) {
#pragma unroll
                for (int j = 0; j < 3; j++) {
                    const float* row = &buf[((tz + i) * SMY + (ty + j)) * SMX + rowoff];
                    const float2 m01 = *reinterpret_cast<const float2*>(row);     // m[x-1],m[x]
                    const float2 m23 = *reinterpret_cast<const float2*>(row + 2); // m[x+1],m[x+2]
                    const int oi = i * 3 + j;
                    ffma2(accA[oi], fpk, pack2(m01.x, m01.y));   // k=0
                    ffma2(accC[oi], fpk, pack2(m23.x, m23.y));   // k=2
                    a1x[oi] = fmaf(f.x, m01.y, a1x[oi]);         // k=1 lo
                    a1y[oi] = fmaf(f.y, m23.x, a1y[oi]);         // k=1 hi
                }
            }
        }

        cur++; if (cur == STAGES) cur = 0;
    }

    const float scale = 0.17677669529663687f;  // 32^{-1/2}
    const int sp = (z * N + y) * N + x;
#pragma unroll
    for (int oi = 0; oi < 9; oi++) {
        unsigned int lo, hi;
        float2 r;

        asm("mov.b64 {%0, %1}, %2;" : "=r"(lo), "=r"(hi) : "l"(accA[oi]));
        r.x = __uint_as_float(lo) * scale;
        r.y = __uint_as_float(hi) * scale;
        *reinterpret_cast<float2*>(out + (oi * 3 + 0) * VOL + sp) = r;

        r.x = a1x[oi] * scale;
        r.y = a1y[oi] * scale;
        *reinterpret_cast<float2*>(out + (oi * 3 + 1) * VOL + sp) = r;

        asm("mov.b64 {%0, %1}, %2;" : "=r"(lo), "=r"(hi) : "l"(accC[oi]));
        r.x = __uint_as_float(lo) * scale;
        r.y = __uint_as_float(hi) * scale;
        *reinterpret_cast<float2*>(out + (oi * 3 + 2) * VOL + sp) = r;
    }
}

extern "C" void kernel_launch(void* const* d_in, const int* in_sizes, int n_in,
                              void* d_out, int out_size)
{
    const float* fixedp  = (const float*)d_in[0];
    const float* movingp = (const float*)d_in[1];
    float* out = (float*)d_out;

    dim3 block(BTX, BTY, BTZ);                 // 256 threads
    dim3 grid(N / TILE_X, N / BTY, N / BTZ);   // 3 x 12 x 48 = 1728 blocks
    wincorr_kernel<<<grid, block>>>(fixedp, movingp, out);
}